// round 1
// baseline (speedup 1.0000x reference)
#include <cuda_runtime.h>
#include <cuda_bf16.h>
#include <cstdint>

// ---------------- problem constants ----------------
#define B       64
#define N       4096
#define D       64
#define H       128
#define NS      8
#define ITERS   3
#define EPSA    1e-8f
#define LN_EPS  1e-5f
#define SCALE   0.125f          // d^-0.5 = 1/8

#define TILE_R  64              // rows per block in kv kernel
#define NB      16              // chunks per batch in attention kernel
#define NPART   (NB*8)          // per-warp partials per batch = 128

// ---------------- device scratch (module scope: allowed) ----------------
__device__ float  g_k[B*N*D];
__device__ float  g_v[B*N*D];
__device__ float  g_slots[B*NS*D];
__device__ float  g_q[B*NS*D];
__device__ float  g_Pp[B*NPART*NS*D];
__device__ float  g_Sp[B*NPART*NS];
__device__ float4 g_wkt4[16*64];          // [d4][c]
__device__ float4 g_wvt4[16*64];
__device__ float  g_WihT[64*192];         // [d][g]
__device__ float  g_WhhT[64*192];
__device__ float  g_W1T[64*128];          // [d][h]
__device__ float  g_W2T[128*64];          // [h][d]
__device__ float  g_WqT[64*64];           // [d][c]

// ---------------- f32x2 helpers ----------------
__device__ __forceinline__ unsigned long long pack2(float x, float y) {
    unsigned long long r;
    asm("mov.b64 %0, {%1,%2};" : "=l"(r) : "f"(x), "f"(y));
    return r;
}
__device__ __forceinline__ float2 unpack2(unsigned long long v) {
    float2 f;
    asm("mov.b64 {%0,%1}, %2;" : "=f"(f.x), "=f"(f.y) : "l"(v));
    return f;
}
__device__ __forceinline__ unsigned long long ffma2(unsigned long long a,
                                                    unsigned long long b,
                                                    unsigned long long c) {
    unsigned long long d;
    asm("fma.rn.f32x2 %0, %1, %2, %3;" : "=l"(d) : "l"(a), "l"(b), "l"(c));
    return d;
}

// ---------------- prep: transpose weights once ----------------
__global__ void k_prep(const float* __restrict__ Wk, const float* __restrict__ Wv,
                       const float* __restrict__ W_ih, const float* __restrict__ W_hh,
                       const float* __restrict__ W1, const float* __restrict__ W2,
                       const float* __restrict__ Wq) {
    int i = blockIdx.x * 256 + threadIdx.x;
    if (i < 1024) {                   // [16][64] float4 per matrix
        int d4 = i >> 6, c = i & 63;
        g_wkt4[i] = *(const float4*)(Wk + c*64 + d4*4);
        g_wvt4[i] = *(const float4*)(Wv + c*64 + d4*4);
    }
    if (i < 12288) {                  // 64 x 192
        int d = i / 192, g = i % 192;
        g_WihT[i] = W_ih[g*64 + d];
        g_WhhT[i] = W_hh[g*64 + d];
    }
    if (i < 8192) {                   // 64 x 128
        int d = i / 128, hh = i % 128;
        g_W1T[i] = W1[hh*64 + d];
    }
    if (i < 8192) {                   // 128 x 64
        int h = i / 64, dd = i % 64;
        g_W2T[i] = W2[dd*128 + h];
    }
    if (i < 4096) {                   // 64 x 64
        int d = i / 64, c = i % 64;
        g_WqT[i] = Wq[c*64 + d];
    }
}

// ---------------- K1: LN(inputs) then k = xWk^T+bk, v = xWv^T+bv ----------------
__global__ __launch_bounds__(256, 3)
void k_ln_kv(const float* __restrict__ inputs,
             const float* __restrict__ bk, const float* __restrict__ bv,
             const float* __restrict__ lnw, const float* __restrict__ lnb) {
    __shared__ __align__(16) float xs[TILE_R*64];
    __shared__ float4 wk4[16*64];
    __shared__ float4 wv4[16*64];

    int tid = threadIdx.x;
    size_t row0 = (size_t)blockIdx.x * TILE_R;

    const float* src = inputs + row0*64;
    for (int i = tid; i < TILE_R*64; i += 256) xs[i] = src[i];
    for (int i = tid; i < 1024; i += 256) {
        wk4[i] = g_wkt4[i];
        wv4[i] = g_wvt4[i];
    }
    __syncthreads();

    int warp = tid >> 5, lane = tid & 31;
    float lw0 = lnw[lane], lw1 = lnw[lane+32];
    float lb0 = lnb[lane], lb1 = lnb[lane+32];
    for (int r = warp; r < TILE_R; r += 8) {
        float v0 = xs[r*64 + lane], v1 = xs[r*64 + 32 + lane];
        float s = v0 + v1;
        #pragma unroll
        for (int o = 16; o; o >>= 1) s += __shfl_xor_sync(~0u, s, o);
        float mu = s * (1.f/64.f);
        float d0 = v0 - mu, d1 = v1 - mu;
        float q = d0*d0 + d1*d1;
        #pragma unroll
        for (int o = 16; o; o >>= 1) q += __shfl_xor_sync(~0u, q, o);
        float rs = rsqrtf(q * (1.f/64.f) + LN_EPS);
        xs[r*64 + lane]      = d0*rs*lw0 + lb0;
        xs[r*64 + 32 + lane] = d1*rs*lw1 + lb1;
    }
    __syncthreads();

    int c  = tid & 63;
    int rb = tid >> 6;              // 0..3
    float bkc = bk[c], bvc = bv[c];
    #pragma unroll
    for (int g = 0; g < 2; ++g) {
        unsigned long long ak[8], av[8];
        #pragma unroll
        for (int t = 0; t < 8; ++t) { ak[t] = 0ull; av[t] = 0ull; }
        #pragma unroll
        for (int d4 = 0; d4 < 16; ++d4) {
            float4 wk = wk4[d4*64 + c];
            float4 wv = wv4[d4*64 + c];
            unsigned long long wkl = pack2(wk.x, wk.y), wkh = pack2(wk.z, wk.w);
            unsigned long long wvl = pack2(wv.x, wv.y), wvh = pack2(wv.z, wv.w);
            #pragma unroll
            for (int t = 0; t < 8; ++t) {
                int r = rb + 32*g + 4*t;
                float4 x = *(const float4*)(xs + r*64 + d4*4);
                unsigned long long xl = pack2(x.x, x.y), xh = pack2(x.z, x.w);
                ak[t] = ffma2(xl, wkl, ak[t]);
                ak[t] = ffma2(xh, wkh, ak[t]);
                av[t] = ffma2(xl, wvl, av[t]);
                av[t] = ffma2(xh, wvh, av[t]);
            }
        }
        #pragma unroll
        for (int t = 0; t < 8; ++t) {
            int r = rb + 32*g + 4*t;
            float2 k2 = unpack2(ak[t]);
            float2 v2 = unpack2(av[t]);
            g_k[(row0 + r)*64 + c] = k2.x + k2.y + bkc;
            g_v[(row0 + r)*64 + c] = v2.x + v2.y + bvc;
        }
    }
}

// ---------------- LN over 8 slot-rows: warp w handles slot w ----------------
__device__ __forceinline__ void ln8(const float* in, float* out,
                                    const float* __restrict__ w,
                                    const float* __restrict__ bia, int tid) {
    int wp = tid >> 5, lane = tid & 31;
    const float* p = in + wp*64;
    float v0 = p[lane], v1 = p[lane+32];
    float s = v0 + v1;
    #pragma unroll
    for (int o = 16; o; o >>= 1) s += __shfl_xor_sync(~0u, s, o);
    float mu = s * (1.f/64.f);
    float d0 = v0 - mu, d1 = v1 - mu;
    float q = d0*d0 + d1*d1;
    #pragma unroll
    for (int o = 16; o; o >>= 1) q += __shfl_xor_sync(~0u, q, o);
    float rs = rsqrtf(q * (1.f/64.f) + LN_EPS);
    out[wp*64 + lane]      = d0*rs*w[lane] + bia[lane];
    out[wp*64 + lane + 32] = d1*rs*w[lane+32] + bia[lane+32];
}

// ---------------- init: slots = mu + sigma*noise; q0 ----------------
__global__ __launch_bounds__(256)
void k_init(const float* __restrict__ noise, const float* __restrict__ mu,
            const float* __restrict__ sg,
            const float* __restrict__ ln_s_w, const float* __restrict__ ln_s_b,
            const float* __restrict__ bq) {
    __shared__ float sl[512], sn[512];
    int b = blockIdx.x, tid = threadIdx.x;
    #pragma unroll
    for (int u = 0; u < 2; ++u) {
        int t = tid + 256*u, dd = t & 63;
        float s = mu[dd] + sg[dd]*noise[b*512 + t];
        sl[t] = s;
        g_slots[b*512 + t] = s;
    }
    __syncthreads();
    ln8(sl, sn, ln_s_w, ln_s_b, tid);
    __syncthreads();
    #pragma unroll
    for (int u = 0; u < 2; ++u) {
        int t = tid + 256*u, j = t >> 6, dd = t & 63;
        float acc = bq[dd];
        const float* sj = sn + j*64;
        for (int d = 0; d < 64; ++d) acc += sj[d]*g_WqT[d*64 + dd];
        g_q[b*512 + t] = acc * SCALE;
    }
}

// ---------------- attention reduction: per-warp partial P, S ----------------
__global__ __launch_bounds__(256, 4)
void k_attn(const int* __restrict__ mask) {
    int b = blockIdx.y, chunk = blockIdx.x;
    int warp = threadIdx.x >> 5, lane = threadIdx.x & 31;
    int jj = lane & 7;
    int db = (lane >> 3) << 4;          // 0,16,32,48

    float qreg[16];
    {
        const float* qp = g_q + b*512 + jj*64 + db;
        #pragma unroll
        for (int i = 0; i < 16; i += 4) {
            float4 t4 = *(const float4*)(qp + i);
            qreg[i] = t4.x; qreg[i+1] = t4.y; qreg[i+2] = t4.z; qreg[i+3] = t4.w;
        }
    }
    float Pacc[16];
    #pragma unroll
    for (int i = 0; i < 16; ++i) Pacc[i] = 0.f;
    float Sacc = 0.f;

    int rowbase = chunk * (N / NB);
    const int* mrow = mask + b*N;
    for (int i = 0; i < (N/NB)/8; ++i) {
        int r = rowbase + i*8 + warp;
        if (__ldg(mrow + r) == 0) continue;
        size_t roff = ((size_t)b*N + r)*64;
        const float4* krow = (const float4*)(g_k + roff) + (db >> 2);
        float dot = 0.f;
        #pragma unroll
        for (int t = 0; t < 4; ++t) {
            float4 k4 = __ldg(krow + t);
            dot += k4.x*qreg[4*t] + k4.y*qreg[4*t+1] + k4.z*qreg[4*t+2] + k4.w*qreg[4*t+3];
        }
        dot += __shfl_xor_sync(~0u, dot, 8);
        dot += __shfl_xor_sync(~0u, dot, 16);
        float mx = dot;
        mx = fmaxf(mx, __shfl_xor_sync(~0u, mx, 1));
        mx = fmaxf(mx, __shfl_xor_sync(~0u, mx, 2));
        mx = fmaxf(mx, __shfl_xor_sync(~0u, mx, 4));
        float e = __expf(dot - mx);
        float den = e;
        den += __shfl_xor_sync(~0u, den, 1);
        den += __shfl_xor_sync(~0u, den, 2);
        den += __shfl_xor_sync(~0u, den, 4);
        float a = __fdividef(e, den) + EPSA;
        Sacc += a;
        const float4* vrow = (const float4*)(g_v + roff) + (db >> 2);
        #pragma unroll
        for (int t = 0; t < 4; ++t) {
            float4 v4 = __ldg(vrow + t);
            Pacc[4*t]   += a*v4.x; Pacc[4*t+1] += a*v4.y;
            Pacc[4*t+2] += a*v4.z; Pacc[4*t+3] += a*v4.w;
        }
    }
    int part = chunk*8 + warp;
    float* pp = g_Pp + ((size_t)b*NPART + part)*512 + jj*64 + db;
    #pragma unroll
    for (int i = 0; i < 16; i += 4)
        *(float4*)(pp + i) = make_float4(Pacc[i], Pacc[i+1], Pacc[i+2], Pacc[i+3]);
    if (db == 0) g_Sp[(b*NPART + part)*8 + jj] = Sacc;
}

// ---------------- slot update: GRU + residual MLP (+ next q) ----------------
__global__ __launch_bounds__(256)
void k_update(const float* __restrict__ b_ih, const float* __restrict__ b_hh,
              const float* __restrict__ b1, const float* __restrict__ b2,
              const float* __restrict__ ln_ff_w, const float* __restrict__ ln_ff_b,
              const float* __restrict__ ln_s_w, const float* __restrict__ ln_s_b,
              const float* __restrict__ bq,
              float* __restrict__ d_out, int last) {
    __shared__ float upd[512], prev[512], snew[512], ffs[512], hid[1024], sfin[512], Ssm[8];
    int b = blockIdx.x, tid = threadIdx.x;

    if (tid < 8) {
        float s = 0.f;
        const float* sp = g_Sp + b*NPART*8 + tid;
        for (int p = 0; p < NPART; ++p) s += sp[p*8];
        Ssm[tid] = s;
    }
    float pr[2];
    #pragma unroll
    for (int u = 0; u < 2; ++u) {
        int t = tid + 256*u;
        float s = 0.f;
        const float* pp = g_Pp + (size_t)b*NPART*512 + t;
        for (int p = 0; p < NPART; ++p) s += pp[(size_t)p*512];
        pr[u] = s;
        prev[t] = g_slots[b*512 + t];
    }
    __syncthreads();
    #pragma unroll
    for (int u = 0; u < 2; ++u) {
        int t = tid + 256*u;
        upd[t] = pr[u] / Ssm[t >> 6];
    }
    __syncthreads();

    // GRU
    #pragma unroll
    for (int u = 0; u < 2; ++u) {
        int t = tid + 256*u, j = t >> 6, dd = t & 63;
        const float* uj = upd + j*64;
        const float* hj = prev + j*64;
        float xr = b_ih[dd], xz = b_ih[64+dd], xn = b_ih[128+dd];
        float hr = b_hh[dd], hz = b_hh[64+dd], hn = b_hh[128+dd];
        for (int d = 0; d < 64; ++d) {
            float uu = uj[d], hh = hj[d];
            const float* wi = g_WihT + d*192;
            const float* wh = g_WhhT + d*192;
            xr += uu*wi[dd]; xz += uu*wi[64+dd]; xn += uu*wi[128+dd];
            hr += hh*wh[dd]; hz += hh*wh[64+dd]; hn += hh*wh[128+dd];
        }
        float rg = 1.f/(1.f + __expf(-(xr + hr)));
        float zg = 1.f/(1.f + __expf(-(xz + hz)));
        float t2 = __expf(2.f*(xn + rg*hn));
        float nn = 1.f - 2.f/(t2 + 1.f);
        snew[t] = (1.f - zg)*nn + zg*prev[t];
    }
    __syncthreads();
    ln8(snew, ffs, ln_ff_w, ln_ff_b, tid);
    __syncthreads();
    #pragma unroll
    for (int u = 0; u < 4; ++u) {
        int t = tid + 256*u, j = t >> 7, hh = t & 127;
        float acc = b1[hh];
        const float* fj = ffs + j*64;
        for (int d = 0; d < 64; ++d) acc += fj[d]*g_W1T[d*128 + hh];
        hid[t] = fmaxf(acc, 0.f);
    }
    __syncthreads();
    #pragma unroll
    for (int u = 0; u < 2; ++u) {
        int t = tid + 256*u, j = t >> 6, dd = t & 63;
        float acc = b2[dd];
        const float* hj = hid + j*128;
        for (int h = 0; h < 128; ++h) acc += hj[h]*g_W2T[h*64 + dd];
        float o = snew[t] + acc;
        sfin[t] = o;
        g_slots[b*512 + t] = o;
        if (last) d_out[b*512 + t] = o;
    }
    if (!last) {
        __syncthreads();
        ln8(sfin, ffs, ln_s_w, ln_s_b, tid);   // reuse ffs as s_n
        __syncthreads();
        #pragma unroll
        for (int u = 0; u < 2; ++u) {
            int t = tid + 256*u, j = t >> 6, dd = t & 63;
            float acc = bq[dd];
            const float* sj = ffs + j*64;
            for (int d = 0; d < 64; ++d) acc += sj[d]*g_WqT[d*64 + dd];
            g_q[b*512 + t] = acc * SCALE;
        }
    }
}

// ---------------- launch ----------------
extern "C" void kernel_launch(void* const* d_in, const int* in_sizes, int n_in,
                              void* d_out, int out_size) {
    const float* inputs     = (const float*)d_in[0];
    const int*   mask       = (const int*)  d_in[1];
    const float* noise      = (const float*)d_in[2];
    const float* slots_mu   = (const float*)d_in[3];
    const float* slots_sig  = (const float*)d_in[4];
    const float* Wq         = (const float*)d_in[5];
    const float* bq         = (const float*)d_in[6];
    const float* Wk         = (const float*)d_in[7];
    const float* bk         = (const float*)d_in[8];
    const float* Wv         = (const float*)d_in[9];
    const float* bv         = (const float*)d_in[10];
    const float* W_ih       = (const float*)d_in[11];
    const float* b_ih       = (const float*)d_in[12];
    const float* W_hh       = (const float*)d_in[13];
    const float* b_hh       = (const float*)d_in[14];
    const float* W1         = (const float*)d_in[15];
    const float* b1         = (const float*)d_in[16];
    const float* W2         = (const float*)d_in[17];
    const float* b2         = (const float*)d_in[18];
    const float* ln_in_w    = (const float*)d_in[19];
    const float* ln_in_b    = (const float*)d_in[20];
    const float* ln_s_w     = (const float*)d_in[21];
    const float* ln_s_b     = (const float*)d_in[22];
    const float* ln_ff_w    = (const float*)d_in[23];
    const float* ln_ff_b    = (const float*)d_in[24];
    float* out = (float*)d_out;

    k_prep<<<48, 256>>>(Wk, Wv, W_ih, W_hh, W1, W2, Wq);
    k_ln_kv<<<(B*N)/TILE_R, 256>>>(inputs, bk, bv, ln_in_w, ln_in_b);
    k_init<<<B, 256>>>(noise, slots_mu, slots_sig, ln_s_w, ln_s_b, bq);
    for (int it = 0; it < ITERS; ++it) {
        k_attn<<<dim3(NB, B), 256>>>(mask);
        k_update<<<B, 256>>>(b_ih, b_hh, b1, b2, ln_ff_w, ln_ff_b,
                             ln_s_w, ln_s_b, bq, out, it == ITERS-1 ? 1 : 0);
    }
}

// round 3
// speedup vs baseline: 1.3053x; 1.3053x over previous
#include <cuda_runtime.h>
#include <cuda_bf16.h>
#include <cstdint>

// ---------------- problem constants ----------------
#define B       64
#define N       4096
#define D       64
#define H       128
#define NS      8
#define ITERS   3
#define EPSA    1e-8f
#define LN_EPS  1e-5f
#define SCALE   0.125f          // d^-0.5 = 1/8

#define TILE_R  64              // rows per block in kv kernel
#define NB      16              // chunks per batch in attention kernel  -> NPART = 16

// ---------------- device scratch ----------------
__device__ float  g_k[B*N*D];          // zero-init; masked rows never written (stay 0)
__device__ float  g_v[B*N*D];
__device__ float  g_slots[B*NS*D];
__device__ float  g_q[B*NS*D];
__device__ float  g_Pp[B*NB*NS*D];
__device__ float  g_Sp[B*NB*NS];
__device__ unsigned long long g_wk2[32*64];   // [d2][c] packed pair (Wk[c][2d2], Wk[c][2d2+1])
__device__ unsigned long long g_wv2[32*64];
__device__ float  g_WihT[64*192];         // [d][g]
__device__ float  g_WhhT[64*192];
__device__ float  g_W1T[64*128];          // [d][h]
__device__ float  g_W2T[128*64];          // [h][d]
__device__ float  g_WqT[64*64];           // [d][c]

// ---------------- f32x2 helpers ----------------
__device__ __forceinline__ unsigned long long packf2(float x, float y) {
    unsigned long long r;
    asm("mov.b64 %0, {%1,%2};" : "=l"(r) : "f"(x), "f"(y));
    return r;
}
__device__ __forceinline__ float2 unpackf2(unsigned long long v) {
    float2 f;
    asm("mov.b64 {%0,%1}, %2;" : "=f"(f.x), "=f"(f.y) : "l"(v));
    return f;
}
__device__ __forceinline__ unsigned long long ffma2(unsigned long long a,
                                                    unsigned long long b,
                                                    unsigned long long c) {
    unsigned long long d;
    asm("fma.rn.f32x2 %0, %1, %2, %3;" : "=l"(d) : "l"(a), "l"(b), "l"(c));
    return d;
}

// ---------------- prep: transpose/pack weights once ----------------
__global__ void k_prep(const float* __restrict__ Wk, const float* __restrict__ Wv,
                       const float* __restrict__ W_ih, const float* __restrict__ W_hh,
                       const float* __restrict__ W1, const float* __restrict__ W2,
                       const float* __restrict__ Wq) {
    int i = blockIdx.x * 256 + threadIdx.x;
    if (i < 2048) {                   // [32][64] ull pairs
        int d2 = i >> 6, c = i & 63;
        float2 fk = *(const float2*)(Wk + c*64 + d2*2);
        float2 fv = *(const float2*)(Wv + c*64 + d2*2);
        g_wk2[i] = packf2(fk.x, fk.y);
        g_wv2[i] = packf2(fv.x, fv.y);
    }
    if (i < 12288) {                  // 64 x 192
        int d = i / 192, g = i % 192;
        g_WihT[i] = W_ih[g*64 + d];
        g_WhhT[i] = W_hh[g*64 + d];
    }
    if (i < 8192) {                   // 64 x 128
        int d = i / 128, hh = i % 128;
        g_W1T[i] = W1[hh*64 + d];
    }
    if (i < 8192) {                   // 128 x 64
        int h = i / 64, dd = i % 64;
        g_W2T[i] = W2[dd*128 + h];
    }
    if (i < 4096) {                   // 64 x 64
        int d = i / 64, c = i % 64;
        g_WqT[i] = Wq[c*64 + d];
    }
}

// ---------------- K1: mask-compact + LN + k/v GEMM ----------------
__global__ __launch_bounds__(256, 4)
void k_ln_kv(const float* __restrict__ inputs, const int* __restrict__ mask,
             const float* __restrict__ bk, const float* __restrict__ bv,
             const float* __restrict__ lnw, const float* __restrict__ lnb) {
    __shared__ __align__(16) float xs[TILE_R*64];           // compacted LN'd rows
    __shared__ unsigned long long wk2s[32*64];
    __shared__ unsigned long long wv2s[32*64];
    __shared__ int   cidx[TILE_R];
    __shared__ int   wcnt[2];

    int tid = threadIdx.x;
    size_t row0 = (size_t)blockIdx.x * TILE_R;

    // weights -> smem
    for (int i = tid; i < 2048; i += 256) {
        wk2s[i] = g_wk2[i];
        wv2s[i] = g_wv2[i];
    }

    // --- compaction (threads 0..63 = warps 0,1) ---
    int lane = tid & 31, warp = tid >> 5;
    if (tid < 64) {
        int mm = mask[row0 + tid] != 0;
        unsigned bal = __ballot_sync(~0u, mm);
        int before = __popc(bal & ((1u << lane) - 1u));
        if (lane == 0) wcnt[warp] = __popc(bal);
        __syncwarp();
        int base = (warp == 1) ? __popc(__ballot_sync(~0u, mm) & 0u) : 0; // placeholder
        // need warp0 count for warp1: read after syncthreads below instead
        cidx[tid] = (mm ? before : -1);   // temp store local pos
    }
    __syncthreads();
    int act = wcnt[0] + wcnt[1];
    // finalize cidx: rebuild mapping (threads 0..63)
    if (tid < 64) {
        int mm = mask[row0 + tid] != 0;
        if (mm) {
            int pos = cidx[tid] + ((tid >= 32) ? wcnt[0] : 0);
            // pos may collide with reads above; use syncthreads then write
            cidx[tid] = pos;    // will scatter below after sync
        }
    }
    __syncthreads();
    // scatter: build compact->orig map in place (use second half trick)
    __shared__ int cmap[TILE_R];
    if (tid < 64) {
        int mm = mask[row0 + tid] != 0;
        if (mm) cmap[cidx[tid]] = tid;
    }
    int pad = (act + 15) & ~15;
    // zero pad region of xs
    for (int i = tid; i < (pad - act) * 64; i += 256) xs[act*64 + i] = 0.f;
    __syncthreads();

    // --- LN on active rows only (each warp strides over compact indices) ---
    {
        float lw0 = lnw[lane], lw1 = lnw[lane+32];
        float lb0 = lnb[lane], lb1 = lnb[lane+32];
        for (int ci = warp; ci < act; ci += 8) {
            int r = cmap[ci];
            const float* src = inputs + (row0 + r)*64;
            float v0 = src[lane], v1 = src[lane+32];
            float s = v0 + v1;
            #pragma unroll
            for (int o = 16; o; o >>= 1) s += __shfl_xor_sync(~0u, s, o);
            float mu = s * (1.f/64.f);
            float d0 = v0 - mu, d1 = v1 - mu;
            float q = d0*d0 + d1*d1;
            #pragma unroll
            for (int o = 16; o; o >>= 1) q += __shfl_xor_sync(~0u, q, o);
            float rs = rsqrtf(q * (1.f/64.f) + LN_EPS);
            xs[ci*64 + lane]      = d0*rs*lw0 + lb0;
            xs[ci*64 + 32 + lane] = d1*rs*lw1 + lb1;
        }
    }
    __syncthreads();

    // --- GEMM over compacted rows, groups of 16 ---
    int c  = tid & 63;
    int rb = tid >> 6;              // 0..3
    float bkc = bk[c], bvc = bv[c];
    const unsigned long long* xs2 = reinterpret_cast<const unsigned long long*>(xs);
    int G = pad >> 4;
    for (int g = 0; g < G; ++g) {
        unsigned long long ak[4], av[4];
        #pragma unroll
        for (int t = 0; t < 4; ++t) { ak[t] = 0ull; av[t] = 0ull; }
        #pragma unroll
        for (int d2 = 0; d2 < 32; ++d2) {
            unsigned long long wk = wk2s[d2*64 + c];
            unsigned long long wv = wv2s[d2*64 + c];
            #pragma unroll
            for (int t = 0; t < 4; ++t) {
                int ci = g*16 + rb + 4*t;
                unsigned long long x = xs2[ci*32 + d2];
                ak[t] = ffma2(x, wk, ak[t]);
                av[t] = ffma2(x, wv, av[t]);
            }
        }
        #pragma unroll
        for (int t = 0; t < 4; ++t) {
            int ci = g*16 + rb + 4*t;
            if (ci < act) {
                int orow = cmap[ci];
                float2 k2 = unpackf2(ak[t]);
                float2 v2 = unpackf2(av[t]);
                g_k[(row0 + orow)*64 + c] = k2.x + k2.y + bkc;
                g_v[(row0 + orow)*64 + c] = v2.x + v2.y + bvc;
            }
        }
    }
}

// ---------------- LN over 8 slot-rows: warp w handles slot w ----------------
__device__ __forceinline__ void ln8(const float* in, float* out,
                                    const float* __restrict__ w,
                                    const float* __restrict__ bia, int tid) {
    int wp = tid >> 5, lane = tid & 31;
    const float* p = in + wp*64;
    float v0 = p[lane], v1 = p[lane+32];
    float s = v0 + v1;
    #pragma unroll
    for (int o = 16; o; o >>= 1) s += __shfl_xor_sync(~0u, s, o);
    float mu = s * (1.f/64.f);
    float d0 = v0 - mu, d1 = v1 - mu;
    float q = d0*d0 + d1*d1;
    #pragma unroll
    for (int o = 16; o; o >>= 1) q += __shfl_xor_sync(~0u, q, o);
    float rs = rsqrtf(q * (1.f/64.f) + LN_EPS);
    out[wp*64 + lane]      = d0*rs*w[lane] + bia[lane];
    out[wp*64 + lane + 32] = d1*rs*w[lane+32] + bia[lane+32];
}

// ---------------- init: slots = mu + sigma*noise; q0 ----------------
__global__ __launch_bounds__(256)
void k_init(const float* __restrict__ noise, const float* __restrict__ mu,
            const float* __restrict__ sg,
            const float* __restrict__ ln_s_w, const float* __restrict__ ln_s_b,
            const float* __restrict__ bq) {
    __shared__ float sl[512], sn[512];
    int b = blockIdx.x, tid = threadIdx.x;
    #pragma unroll
    for (int u = 0; u < 2; ++u) {
        int t = tid + 256*u, dd = t & 63;
        float s = mu[dd] + sg[dd]*noise[b*512 + t];
        sl[t] = s;
        g_slots[b*512 + t] = s;
    }
    __syncthreads();
    ln8(sl, sn, ln_s_w, ln_s_b, tid);
    __syncthreads();
    #pragma unroll
    for (int u = 0; u < 2; ++u) {
        int t = tid + 256*u, j = t >> 6, dd = t & 63;
        float acc = bq[dd];
        const float* sj = sn + j*64;
        for (int d = 0; d < 64; ++d) acc += sj[d]*g_WqT[d*64 + dd];
        g_q[b*512 + t] = acc * SCALE;
    }
}

// ---------------- attention: branchless, 2-row unroll, block-level partials ----------------
__global__ __launch_bounds__(256)
void k_attn(const int* __restrict__ mask) {
    __shared__ float redP[8*512];
    __shared__ float redS[64];

    int b = blockIdx.y, chunk = blockIdx.x;
    int warp = threadIdx.x >> 5, lane = threadIdx.x & 31;
    int jj = lane & 7;
    int f4 = (lane >> 3) << 2;          // float4 index into row: 0,4,8,12

    float q[16];
    {
        const float4* qp = (const float4*)(g_q + b*512 + jj*64) + f4;
        #pragma unroll
        for (int i = 0; i < 4; ++i) {
            float4 t4 = qp[i];
            q[4*i] = t4.x; q[4*i+1] = t4.y; q[4*i+2] = t4.z; q[4*i+3] = t4.w;
        }
    }
    float P[16];
    #pragma unroll
    for (int i = 0; i < 16; ++i) P[i] = 0.f;
    float S = 0.f;

    int rbase = chunk * 256 + warp * 32;
    const float* kb = g_k + ((size_t)b*N + rbase)*64;
    const float* vb = g_v + ((size_t)b*N + rbase)*64;
    const int*  mb  = mask + b*N + rbase;

    for (int i = 0; i < 16; ++i) {
        int2 mm = *(const int2*)(mb + i*2);
        const float4* kp0 = (const float4*)(kb + (i*2    )*64) + f4;
        const float4* kp1 = (const float4*)(kb + (i*2 + 1)*64) + f4;
        float4 a0 = kp0[0], a1 = kp0[1], a2 = kp0[2], a3 = kp0[3];
        float4 b0 = kp1[0], b1 = kp1[1], b2 = kp1[2], b3 = kp1[3];

        float dA = a0.x*q[0]+a0.y*q[1]+a0.z*q[2]+a0.w*q[3]
                 + a1.x*q[4]+a1.y*q[5]+a1.z*q[6]+a1.w*q[7]
                 + a2.x*q[8]+a2.y*q[9]+a2.z*q[10]+a2.w*q[11]
                 + a3.x*q[12]+a3.y*q[13]+a3.z*q[14]+a3.w*q[15];
        float dB = b0.x*q[0]+b0.y*q[1]+b0.z*q[2]+b0.w*q[3]
                 + b1.x*q[4]+b1.y*q[5]+b1.z*q[6]+b1.w*q[7]
                 + b2.x*q[8]+b2.y*q[9]+b2.z*q[10]+b2.w*q[11]
                 + b3.x*q[12]+b3.y*q[13]+b3.z*q[14]+b3.w*q[15];

        dA += __shfl_xor_sync(~0u, dA, 8);  dB += __shfl_xor_sync(~0u, dB, 8);
        dA += __shfl_xor_sync(~0u, dA, 16); dB += __shfl_xor_sync(~0u, dB, 16);

        float mA = dA, mB = dB;
        mA = fmaxf(mA, __shfl_xor_sync(~0u, mA, 1)); mB = fmaxf(mB, __shfl_xor_sync(~0u, mB, 1));
        mA = fmaxf(mA, __shfl_xor_sync(~0u, mA, 2)); mB = fmaxf(mB, __shfl_xor_sync(~0u, mB, 2));
        mA = fmaxf(mA, __shfl_xor_sync(~0u, mA, 4)); mB = fmaxf(mB, __shfl_xor_sync(~0u, mB, 4));
        float eA = __expf(dA - mA), eB = __expf(dB - mB);
        float nA = eA, nB = eB;
        nA += __shfl_xor_sync(~0u, nA, 1); nB += __shfl_xor_sync(~0u, nB, 1);
        nA += __shfl_xor_sync(~0u, nA, 2); nB += __shfl_xor_sync(~0u, nB, 2);
        nA += __shfl_xor_sync(~0u, nA, 4); nB += __shfl_xor_sync(~0u, nB, 4);
        float aA = __fdividef(eA, nA) + EPSA;
        float aB = __fdividef(eB, nB) + EPSA;
        aA = mm.x ? aA : 0.f;
        aB = mm.y ? aB : 0.f;
        S += aA + aB;

        const float4* vp0 = (const float4*)(vb + (i*2    )*64) + f4;
        const float4* vp1 = (const float4*)(vb + (i*2 + 1)*64) + f4;
        float4 v0 = vp0[0], v1 = vp0[1], v2 = vp0[2], v3 = vp0[3];
        float4 w0 = vp1[0], w1 = vp1[1], w2 = vp1[2], w3 = vp1[3];
        P[0]  += aA*v0.x + aB*w0.x;  P[1]  += aA*v0.y + aB*w0.y;
        P[2]  += aA*v0.z + aB*w0.z;  P[3]  += aA*v0.w + aB*w0.w;
        P[4]  += aA*v1.x + aB*w1.x;  P[5]  += aA*v1.y + aB*w1.y;
        P[6]  += aA*v1.z + aB*w1.z;  P[7]  += aA*v1.w + aB*w1.w;
        P[8]  += aA*v2.x + aB*w2.x;  P[9]  += aA*v2.y + aB*w2.y;
        P[10] += aA*v2.z + aB*w2.z;  P[11] += aA*v2.w + aB*w2.w;
        P[12] += aA*v3.x + aB*w3.x;  P[13] += aA*v3.y + aB*w3.y;
        P[14] += aA*v3.z + aB*w3.z;  P[15] += aA*v3.w + aB*w3.w;
    }

    // block-level reduction of partials
    float* rp = redP + warp*512 + jj*64 + f4*4;
    #pragma unroll
    for (int i = 0; i < 4; ++i)
        *(float4*)(rp + 4*i) = make_float4(P[4*i], P[4*i+1], P[4*i+2], P[4*i+3]);
    if ((lane >> 3) == 0) redS[warp*8 + jj] = S;
    __syncthreads();

    int tid = threadIdx.x;
    #pragma unroll
    for (int u = 0; u < 2; ++u) {
        int t = tid + 256*u;
        float s = 0.f;
        #pragma unroll
        for (int w = 0; w < 8; ++w) s += redP[w*512 + t];
        g_Pp[((size_t)b*NB + chunk)*512 + t] = s;
    }
    if (tid < 8) {
        float s = 0.f;
        #pragma unroll
        for (int w = 0; w < 8; ++w) s += redS[w*8 + tid];
        g_Sp[(b*NB + chunk)*8 + tid] = s;
    }
}

// ---------------- slot update: GRU + residual MLP (+ next q) ----------------
__global__ __launch_bounds__(256)
void k_update(const float* __restrict__ b_ih, const float* __restrict__ b_hh,
              const float* __restrict__ b1, const float* __restrict__ b2,
              const float* __restrict__ ln_ff_w, const float* __restrict__ ln_ff_b,
              const float* __restrict__ ln_s_w, const float* __restrict__ ln_s_b,
              const float* __restrict__ bq,
              float* __restrict__ d_out, int last) {
    __shared__ float upd[512], prev[512], snew[512], ffs[512], hid[1024], sfin[512], Ssm[8];
    int b = blockIdx.x, tid = threadIdx.x;

    if (tid < 8) {
        float s = 0.f;
        const float* sp = g_Sp + b*NB*8 + tid;
        #pragma unroll
        for (int p = 0; p < NB; ++p) s += sp[p*8];
        Ssm[tid] = s;
    }
    float pr[2];
    #pragma unroll
    for (int u = 0; u < 2; ++u) {
        int t = tid + 256*u;
        float s = 0.f;
        const float* pp = g_Pp + (size_t)b*NB*512 + t;
        #pragma unroll
        for (int p = 0; p < NB; ++p) s += pp[p*512];
        pr[u] = s;
        prev[t] = g_slots[b*512 + t];
    }
    __syncthreads();
    #pragma unroll
    for (int u = 0; u < 2; ++u) {
        int t = tid + 256*u;
        upd[t] = pr[u] / Ssm[t >> 6];
    }
    __syncthreads();

    // GRU
    #pragma unroll
    for (int u = 0; u < 2; ++u) {
        int t = tid + 256*u, j = t >> 6, dd = t & 63;
        const float* uj = upd + j*64;
        const float* hj = prev + j*64;
        float xr = b_ih[dd], xz = b_ih[64+dd], xn = b_ih[128+dd];
        float hr = b_hh[dd], hz = b_hh[64+dd], hn = b_hh[128+dd];
        #pragma unroll 8
        for (int d = 0; d < 64; ++d) {
            float uu = uj[d], hh = hj[d];
            const float* wi = g_WihT + d*192;
            const float* wh = g_WhhT + d*192;
            xr += uu*wi[dd]; xz += uu*wi[64+dd]; xn += uu*wi[128+dd];
            hr += hh*wh[dd]; hz += hh*wh[64+dd]; hn += hh*wh[128+dd];
        }
        float rg = 1.f/(1.f + __expf(-(xr + hr)));
        float zg = 1.f/(1.f + __expf(-(xz + hz)));
        float t2 = __expf(2.f*(xn + rg*hn));
        float nn = 1.f - 2.f/(t2 + 1.f);
        snew[t] = (1.f - zg)*nn + zg*prev[t];
    }
    __syncthreads();
    ln8(snew, ffs, ln_ff_w, ln_ff_b, tid);
    __syncthreads();
    #pragma unroll
    for (int u = 0; u < 4; ++u) {
        int t = tid + 256*u, j = t >> 7, hh = t & 127;
        float acc = b1[hh];
        const float* fj = ffs + j*64;
        #pragma unroll 8
        for (int d = 0; d < 64; ++d) acc += fj[d]*g_W1T[d*128 + hh];
        hid[t] = fmaxf(acc, 0.f);
    }
    __syncthreads();
    #pragma unroll
    for (int u = 0; u < 2; ++u) {
        int t = tid + 256*u, j = t >> 6, dd = t & 63;
        float acc = b2[dd];
        const float* hj = hid + j*128;
        #pragma unroll 8
        for (int h = 0; h < 128; ++h) acc += hj[h]*g_W2T[h*64 + dd];
        float o = snew[t] + acc;
        sfin[t] = o;
        g_slots[b*512 + t] = o;
        if (last) d_out[b*512 + t] = o;
    }
    if (!last) {
        __syncthreads();
        ln8(sfin, ffs, ln_s_w, ln_s_b, tid);   // reuse ffs as s_n
        __syncthreads();
        #pragma unroll
        for (int u = 0; u < 2; ++u) {
            int t = tid + 256*u, j = t >> 6, dd = t & 63;
            float acc = bq[dd];
            const float* sj = ffs + j*64;
            #pragma unroll 8
            for (int d = 0; d < 64; ++d) acc += sj[d]*g_WqT[d*64 + dd];
            g_q[b*512 + t] = acc * SCALE;
        }
    }
}

// ---------------- launch ----------------
extern "C" void kernel_launch(void* const* d_in, const int* in_sizes, int n_in,
                              void* d_out, int out_size) {
    const float* inputs     = (const float*)d_in[0];
    const int*   mask       = (const int*)  d_in[1];
    const float* noise      = (const float*)d_in[2];
    const float* slots_mu   = (const float*)d_in[3];
    const float* slots_sig  = (const float*)d_in[4];
    const float* Wq         = (const float*)d_in[5];
    const float* bq         = (const float*)d_in[6];
    const float* Wk         = (const float*)d_in[7];
    const float* bk         = (const float*)d_in[8];
    const float* Wv         = (const float*)d_in[9];
    const float* bv         = (const float*)d_in[10];
    const float* W_ih       = (const float*)d_in[11];
    const float* b_ih       = (const float*)d_in[12];
    const float* W_hh       = (const float*)d_in[13];
    const float* b_hh       = (const float*)d_in[14];
    const float* W1         = (const float*)d_in[15];
    const float* b1         = (const float*)d_in[16];
    const float* W2         = (const float*)d_in[17];
    const float* b2         = (const float*)d_in[18];
    const float* ln_in_w    = (const float*)d_in[19];
    const float* ln_in_b    = (const float*)d_in[20];
    const float* ln_s_w     = (const float*)d_in[21];
    const float* ln_s_b     = (const float*)d_in[22];
    const float* ln_ff_w    = (const float*)d_in[23];
    const float* ln_ff_b    = (const float*)d_in[24];
    float* out = (float*)d_out;

    k_prep<<<48, 256>>>(Wk, Wv, W_ih, W_hh, W1, W2, Wq);
    k_ln_kv<<<(B*N)/TILE_R, 256>>>(inputs, mask, bk, bv, ln_in_w, ln_in_b);
    k_init<<<B, 256>>>(noise, slots_mu, slots_sig, ln_s_w, ln_s_b, bq);
    for (int it = 0; it < ITERS; ++it) {
        k_attn<<<dim3(NB, B), 256>>>(mask);
        k_update<<<B, 256>>>(b_ih, b_hh, b1, b2, ln_ff_w, ln_ff_b,
                             ln_s_w, ln_s_b, bq, out, it == ITERS-1 ? 1 : 0);
    }
}

// round 4
// speedup vs baseline: 2.4403x; 1.8696x over previous
#include <cuda_runtime.h>
#include <cuda_bf16.h>
#include <cstdint>

// ---------------- problem constants ----------------
#define B       64
#define N       4096
#define D       64
#define H       128
#define NS      8
#define ITERS   3
#define EPSA    1e-8f
#define LN_EPS  1e-5f
#define SCALE   0.125f

#define TILE_R  64              // rows per block in kv kernel
#define NB      16              // chunks per batch in attention (256 rows each)
#define DSTR    257             // padded stride for dots/att smem

// ---------------- device scratch ----------------
__device__ float  g_k[B*N*D];          // compacted per 64-row region
__device__ float  g_v[B*N*D];
__device__ int    g_cnt[B*N/TILE_R];   // active rows per 64-row region
__device__ float  g_slots[B*NS*D];
__device__ float  g_q[B*NS*D];
__device__ float  g_Pp[B*NB*NS*D];
__device__ float  g_Sp[B*NB*NS];
__device__ ulonglong2 g_wk2v[16*64];   // [d4][c]: pairs (f32x2) covering 4 d values
__device__ ulonglong2 g_wv2v[16*64];
__device__ float  g_WihT[64*192];      // [d][g]
__device__ float  g_WhhT[64*192];
__device__ float  g_W1T[64*128];       // [d][h]
__device__ float  g_W2T[128*64];       // [h][d]
__device__ float  g_WqT[64*64];        // [d][c]

// ---------------- f32x2 helpers ----------------
__device__ __forceinline__ unsigned long long packf2(float x, float y) {
    unsigned long long r;
    asm("mov.b64 %0, {%1,%2};" : "=l"(r) : "f"(x), "f"(y));
    return r;
}
__device__ __forceinline__ float2 unpackf2(unsigned long long v) {
    float2 f;
    asm("mov.b64 {%0,%1}, %2;" : "=f"(f.x), "=f"(f.y) : "l"(v));
    return f;
}
__device__ __forceinline__ unsigned long long ffma2(unsigned long long a,
                                                    unsigned long long b,
                                                    unsigned long long c) {
    unsigned long long d;
    asm("fma.rn.f32x2 %0, %1, %2, %3;" : "=l"(d) : "l"(a), "l"(b), "l"(c));
    return d;
}

// ---------------- prep: transpose/pack weights once ----------------
__global__ void k_prep(const float* __restrict__ Wk, const float* __restrict__ Wv,
                       const float* __restrict__ W_ih, const float* __restrict__ W_hh,
                       const float* __restrict__ W1, const float* __restrict__ W2,
                       const float* __restrict__ Wq) {
    int i = blockIdx.x * 256 + threadIdx.x;
    if (i < 1024) {                   // [16][64]
        int d4 = i >> 6, c = i & 63;
        float4 fk = *(const float4*)(Wk + c*64 + d4*4);
        float4 fv = *(const float4*)(Wv + c*64 + d4*4);
        ulonglong2 k2, v2;
        k2.x = packf2(fk.x, fk.y); k2.y = packf2(fk.z, fk.w);
        v2.x = packf2(fv.x, fv.y); v2.y = packf2(fv.z, fv.w);
        g_wk2v[i] = k2;
        g_wv2v[i] = v2;
    }
    if (i < 12288) {                  // 64 x 192
        int d = i / 192, g = i % 192;
        g_WihT[i] = W_ih[g*64 + d];
        g_WhhT[i] = W_hh[g*64 + d];
    }
    if (i < 8192) {                   // 64 x 128
        int d = i / 128, hh = i % 128;
        g_W1T[i] = W1[hh*64 + d];
    }
    if (i < 8192) {                   // 128 x 64
        int h = i / 64, dd = i % 64;
        g_W2T[i] = W2[dd*128 + h];
    }
    if (i < 4096) {                   // 64 x 64
        int d = i / 64, c = i % 64;
        g_WqT[i] = Wq[c*64 + d];
    }
}

// ---------------- K1: mask-compact + LN + k/v GEMM (compacted store) ----------------
__global__ __launch_bounds__(256, 4)
void k_ln_kv(const float* __restrict__ inputs, const int* __restrict__ mask,
             const float* __restrict__ bk, const float* __restrict__ bv,
             const float* __restrict__ lnw, const float* __restrict__ lnb) {
    __shared__ __align__(16) float xs[TILE_R*64];   // compacted LN'd rows (16KB)
    __shared__ int tpos[TILE_R];
    __shared__ int cmap[TILE_R];
    __shared__ int wc[2];

    int tid = threadIdx.x;
    int lane = tid & 31, warp = tid >> 5;
    size_t row0 = (size_t)blockIdx.x * TILE_R;

    // --- compaction (threads 0..63) ---
    if (tid < 64) {
        int mm = mask[row0 + tid] != 0;
        unsigned bal = __ballot_sync(~0u, mm);
        if (lane == 0) wc[warp] = __popc(bal);
        tpos[tid] = mm ? __popc(bal & ((1u << lane) - 1u)) : -1;
    }
    __syncthreads();
    int act = wc[0] + wc[1];
    if (tid < 64 && tpos[tid] >= 0)
        cmap[tpos[tid] + (tid >= 32 ? wc[0] : 0)] = tid;
    if (tid == 0) g_cnt[blockIdx.x] = act;
    __syncthreads();

    // --- LN on active rows only ---
    {
        float lw0 = lnw[lane], lw1 = lnw[lane+32];
        float lb0 = lnb[lane], lb1 = lnb[lane+32];
        for (int ci = warp; ci < act; ci += 8) {
            int r = cmap[ci];
            const float* src = inputs + (row0 + r)*64;
            float v0 = src[lane], v1 = src[lane+32];
            float s = v0 + v1;
            #pragma unroll
            for (int o = 16; o; o >>= 1) s += __shfl_xor_sync(~0u, s, o);
            float mu = s * (1.f/64.f);
            float d0 = v0 - mu, d1 = v1 - mu;
            float q = d0*d0 + d1*d1;
            #pragma unroll
            for (int o = 16; o; o >>= 1) q += __shfl_xor_sync(~0u, q, o);
            float rs = rsqrtf(q * (1.f/64.f) + LN_EPS);
            xs[ci*64 + lane]      = d0*rs*lw0 + lb0;
            xs[ci*64 + 32 + lane] = d1*rs*lw1 + lb1;
        }
    }
    __syncthreads();

    // --- GEMM over compacted rows: 32 rows per group, 8 rows per thread ---
    int c  = tid & 63;
    int rb = tid >> 6;              // 0..3
    float bkc = bk[c], bvc = bv[c];
    const ulonglong2* xs2 = reinterpret_cast<const ulonglong2*>(xs);  // [row][16]
    int G = (act + 31) >> 5;
    for (int g = 0; g < G; ++g) {
        unsigned long long ak[8], av[8];
        #pragma unroll
        for (int t = 0; t < 8; ++t) { ak[t] = 0ull; av[t] = 0ull; }
        #pragma unroll
        for (int d4 = 0; d4 < 16; ++d4) {
            ulonglong2 wk = __ldg(g_wk2v + d4*64 + c);
            ulonglong2 wv = __ldg(g_wv2v + d4*64 + c);
            #pragma unroll
            for (int t = 0; t < 8; ++t) {
                int ci = g*32 + rb + 4*t;
                ulonglong2 x = xs2[ci*16 + d4];     // broadcast LDS.128
                ak[t] = ffma2(x.x, wk.x, ak[t]);
                ak[t] = ffma2(x.y, wk.y, ak[t]);
                av[t] = ffma2(x.x, wv.x, av[t]);
                av[t] = ffma2(x.y, wv.y, av[t]);
            }
        }
        #pragma unroll
        for (int t = 0; t < 8; ++t) {
            int ci = g*32 + rb + 4*t;
            if (ci < act) {
                float2 k2 = unpackf2(ak[t]);
                float2 v2 = unpackf2(av[t]);
                g_k[(row0 + ci)*64 + c] = k2.x + k2.y + bkc;   // compacted
                g_v[(row0 + ci)*64 + c] = v2.x + v2.y + bvc;
            }
        }
    }
}

// ---------------- LN over slot rows: warp w handles slot w (nrows warps used) ----------------
__device__ __forceinline__ void lnrows(const float* in, float* out,
                                       const float* __restrict__ w,
                                       const float* __restrict__ bia, int tid, int nrows) {
    int wp = tid >> 5, lane = tid & 31;
    if (wp >= nrows) return;
    const float* p = in + wp*64;
    float v0 = p[lane], v1 = p[lane+32];
    float s = v0 + v1;
    #pragma unroll
    for (int o = 16; o; o >>= 1) s += __shfl_xor_sync(~0u, s, o);
    float mu = s * (1.f/64.f);
    float d0 = v0 - mu, d1 = v1 - mu;
    float q = d0*d0 + d1*d1;
    #pragma unroll
    for (int o = 16; o; o >>= 1) q += __shfl_xor_sync(~0u, q, o);
    float rs = rsqrtf(q * (1.f/64.f) + LN_EPS);
    out[wp*64 + lane]      = d0*rs*w[lane] + bia[lane];
    out[wp*64 + lane + 32] = d1*rs*w[lane+32] + bia[lane+32];
}

// ---------------- init: slots = mu + sigma*noise; q0 ----------------
__global__ __launch_bounds__(256)
void k_init(const float* __restrict__ noise, const float* __restrict__ mu,
            const float* __restrict__ sg,
            const float* __restrict__ ln_s_w, const float* __restrict__ ln_s_b,
            const float* __restrict__ bq) {
    __shared__ float sl[512], sn[512];
    int b = blockIdx.x, tid = threadIdx.x;
    #pragma unroll
    for (int u = 0; u < 2; ++u) {
        int t = tid + 256*u, dd = t & 63;
        float s = mu[dd] + sg[dd]*noise[b*512 + t];
        sl[t] = s;
        g_slots[b*512 + t] = s;
    }
    __syncthreads();
    lnrows(sl, sn, ln_s_w, ln_s_b, tid, 8);
    __syncthreads();
    #pragma unroll
    for (int u = 0; u < 2; ++u) {
        int t = tid + 256*u, j = t >> 6, dd = t & 63;
        float acc = bq[dd];
        const float* sj = sn + j*64;
        for (int d = 0; d < 64; ++d) acc += sj[d]*g_WqT[d*64 + dd];
        g_q[b*512 + t] = acc * SCALE;
    }
}

// ---------------- attention: compacted rows, in-thread softmax ----------------
__global__ __launch_bounds__(256)
void k_attn() {
    __shared__ float dots[8*DSTR];   // [slot][localrow 0..255] padded
    __shared__ float att[8*DSTR];
    __shared__ float redP[8*512];
    __shared__ float redS[64];
    __shared__ int   cnts[4];

    int b = blockIdx.y, chunk = blockIdx.x;
    int tid = threadIdx.x;
    int warp = tid >> 5, lane = tid & 31;
    int jj = lane & 7;
    int gg = lane >> 3;                // 0..3
    int f4 = gg << 2;                  // float4 offset 0,4,8,12

    if (tid < 4) cnts[tid] = g_cnt[b*(N/TILE_R) + chunk*4 + tid];

    float q[16];
    {
        const float4* qp = (const float4*)(g_q + b*512 + jj*64) + f4;
        #pragma unroll
        for (int i = 0; i < 4; ++i) {
            float4 t4 = qp[i];
            q[4*i] = t4.x; q[4*i+1] = t4.y; q[4*i+2] = t4.z; q[4*i+3] = t4.w;
        }
    }
    __syncthreads();

    // Phase A: dots[jj][s*64+r]
    #pragma unroll
    for (int s = 0; s < 4; ++s) {
        int cnt = cnts[s];
        const float* kb = g_k + ((size_t)(b*(N/TILE_R) + chunk*4 + s) * TILE_R) * 64;
        for (int r = warp; r < cnt; r += 8) {
            const float4* kp = (const float4*)(kb + r*64) + f4;
            float4 a0 = kp[0], a1 = kp[1], a2 = kp[2], a3 = kp[3];
            float d = a0.x*q[0]+a0.y*q[1]+a0.z*q[2]+a0.w*q[3]
                    + a1.x*q[4]+a1.y*q[5]+a1.z*q[6]+a1.w*q[7]
                    + a2.x*q[8]+a2.y*q[9]+a2.z*q[10]+a2.w*q[11]
                    + a3.x*q[12]+a3.y*q[13]+a3.z*q[14]+a3.w*q[15];
            d += __shfl_xor_sync(~0u, d, 8);
            d += __shfl_xor_sync(~0u, d, 16);
            if (gg == 0) dots[jj*DSTR + s*64 + r] = d;
        }
    }
    __syncthreads();

    // Phase B: in-thread softmax over 8 slots, one thread per row
    {
        int s = tid >> 6, r = tid & 63;
        if (r < cnts[s]) {
            float d[8];
            #pragma unroll
            for (int j = 0; j < 8; ++j) d[j] = dots[j*DSTR + tid];
            float m = d[0];
            #pragma unroll
            for (int j = 1; j < 8; ++j) m = fmaxf(m, d[j]);
            float e[8], sum = 0.f;
            #pragma unroll
            for (int j = 0; j < 8; ++j) { e[j] = __expf(d[j] - m); sum += e[j]; }
            float inv = __fdividef(1.f, sum);
            #pragma unroll
            for (int j = 0; j < 8; ++j) att[j*DSTR + tid] = e[j]*inv + EPSA;
        }
    }
    __syncthreads();

    // Phase C: P accumulation over own rows
    float P[16];
    #pragma unroll
    for (int i = 0; i < 16; ++i) P[i] = 0.f;
    float S = 0.f;
    #pragma unroll
    for (int s = 0; s < 4; ++s) {
        int cnt = cnts[s];
        const float* vb = g_v + ((size_t)(b*(N/TILE_R) + chunk*4 + s) * TILE_R) * 64;
        for (int r = warp; r < cnt; r += 8) {
            float a = att[jj*DSTR + s*64 + r];
            S += a;
            const float4* vp = (const float4*)(vb + r*64) + f4;
            float4 v0 = vp[0], v1 = vp[1], v2 = vp[2], v3 = vp[3];
            P[0]  += a*v0.x; P[1]  += a*v0.y; P[2]  += a*v0.z; P[3]  += a*v0.w;
            P[4]  += a*v1.x; P[5]  += a*v1.y; P[6]  += a*v1.z; P[7]  += a*v1.w;
            P[8]  += a*v2.x; P[9]  += a*v2.y; P[10] += a*v2.z; P[11] += a*v2.w;
            P[12] += a*v3.x; P[13] += a*v3.y; P[14] += a*v3.z; P[15] += a*v3.w;
        }
    }

    float* rp = redP + warp*512 + jj*64 + f4*4;
    #pragma unroll
    for (int i = 0; i < 4; ++i)
        *(float4*)(rp + 4*i) = make_float4(P[4*i], P[4*i+1], P[4*i+2], P[4*i+3]);
    if (gg == 0) redS[warp*8 + jj] = S;
    __syncthreads();

    #pragma unroll
    for (int u = 0; u < 2; ++u) {
        int t = tid + 256*u;
        float s = 0.f;
        #pragma unroll
        for (int w = 0; w < 8; ++w) s += redP[w*512 + t];
        g_Pp[((size_t)b*NB + chunk)*512 + t] = s;
    }
    if (tid < 8) {
        float s = 0.f;
        #pragma unroll
        for (int w = 0; w < 8; ++w) s += redS[w*8 + tid];
        g_Sp[(b*NB + chunk)*8 + tid] = s;
    }
}

// ---------------- slot update: GRU + residual MLP (+ next q); 4 slots/block ----------------
__global__ __launch_bounds__(256)
void k_update(const float* __restrict__ b_ih, const float* __restrict__ b_hh,
              const float* __restrict__ b1, const float* __restrict__ b2,
              const float* __restrict__ ln_ff_w, const float* __restrict__ ln_ff_b,
              const float* __restrict__ ln_s_w, const float* __restrict__ ln_s_b,
              const float* __restrict__ bq,
              float* __restrict__ d_out, int last) {
    __shared__ float upd[256], prev[256], snew[256], ffs[256], hid[512], sfin[256], Ssm[4];
    int b = blockIdx.y, half = blockIdx.x, tid = threadIdx.x;
    int j0 = half * 4;                       // first slot of this block
    int j = tid >> 6, dd = tid & 63;         // local slot 0..3, dim
    int J = j0 + j;                          // global slot

    if (tid < 4) {
        float s = 0.f;
        const float* sp = g_Sp + b*NB*8 + j0 + tid;
        #pragma unroll
        for (int p = 0; p < NB; ++p) s += sp[p*8];
        Ssm[tid] = s;
    }
    float pr;
    {
        float s = 0.f;
        const float* pp = g_Pp + (size_t)b*NB*512 + J*64 + dd;
        #pragma unroll
        for (int p = 0; p < NB; ++p) s += pp[p*512];
        pr = s;
        prev[tid] = g_slots[b*512 + J*64 + dd];
    }
    __syncthreads();
    upd[tid] = pr / Ssm[j];
    __syncthreads();

    // GRU: one output per thread
    {
        const float* uj = upd + j*64;
        const float* hj = prev + j*64;
        float xr = b_ih[dd], xz = b_ih[64+dd], xn = b_ih[128+dd];
        float hr = b_hh[dd], hz = b_hh[64+dd], hn = b_hh[128+dd];
        #pragma unroll 8
        for (int d = 0; d < 64; ++d) {
            float uu = uj[d], hh = hj[d];
            const float* wi = g_WihT + d*192;
            const float* wh = g_WhhT + d*192;
            xr += uu*wi[dd]; xz += uu*wi[64+dd]; xn += uu*wi[128+dd];
            hr += hh*wh[dd]; hz += hh*wh[64+dd]; hn += hh*wh[128+dd];
        }
        float rg = 1.f/(1.f + __expf(-(xr + hr)));
        float zg = 1.f/(1.f + __expf(-(xz + hz)));
        float t2 = __expf(2.f*(xn + rg*hn));
        float nn = 1.f - 2.f/(t2 + 1.f);
        snew[tid] = (1.f - zg)*nn + zg*prev[tid];
    }
    __syncthreads();
    lnrows(snew, ffs, ln_ff_w, ln_ff_b, tid, 4);
    __syncthreads();
    #pragma unroll
    for (int u = 0; u < 2; ++u) {
        int t = tid + 256*u, jl = t >> 7, hh = t & 127;
        float acc = b1[hh];
        const float* fj = ffs + jl*64;
        #pragma unroll 8
        for (int d = 0; d < 64; ++d) acc += fj[d]*g_W1T[d*128 + hh];
        hid[t] = fmaxf(acc, 0.f);
    }
    __syncthreads();
    {
        float acc = b2[dd];
        const float* hj = hid + j*128;
        #pragma unroll 8
        for (int h = 0; h < 128; ++h) acc += hj[h]*g_W2T[h*64 + dd];
        float o = snew[tid] + acc;
        sfin[tid] = o;
        g_slots[b*512 + J*64 + dd] = o;
        if (last) d_out[b*512 + J*64 + dd] = o;
    }
    if (!last) {
        __syncthreads();
        lnrows(sfin, ffs, ln_s_w, ln_s_b, tid, 4);   // reuse ffs as s_n
        __syncthreads();
        {
            float acc = bq[dd];
            const float* sj = ffs + j*64;
            #pragma unroll 8
            for (int d = 0; d < 64; ++d) acc += sj[d]*g_WqT[d*64 + dd];
            g_q[b*512 + J*64 + dd] = acc * SCALE;
        }
    }
}

// ---------------- launch ----------------
extern "C" void kernel_launch(void* const* d_in, const int* in_sizes, int n_in,
                              void* d_out, int out_size) {
    const float* inputs     = (const float*)d_in[0];
    const int*   mask       = (const int*)  d_in[1];
    const float* noise      = (const float*)d_in[2];
    const float* slots_mu   = (const float*)d_in[3];
    const float* slots_sig  = (const float*)d_in[4];
    const float* Wq         = (const float*)d_in[5];
    const float* bq         = (const float*)d_in[6];
    const float* Wk         = (const float*)d_in[7];
    const float* bk         = (const float*)d_in[8];
    const float* Wv         = (const float*)d_in[9];
    const float* bv         = (const float*)d_in[10];
    const float* W_ih       = (const float*)d_in[11];
    const float* b_ih       = (const float*)d_in[12];
    const float* W_hh       = (const float*)d_in[13];
    const float* b_hh       = (const float*)d_in[14];
    const float* W1         = (const float*)d_in[15];
    const float* b1         = (const float*)d_in[16];
    const float* W2         = (const float*)d_in[17];
    const float* b2         = (const float*)d_in[18];
    const float* ln_in_w    = (const float*)d_in[19];
    const float* ln_in_b    = (const float*)d_in[20];
    const float* ln_s_w     = (const float*)d_in[21];
    const float* ln_s_b     = (const float*)d_in[22];
    const float* ln_ff_w    = (const float*)d_in[23];
    const float* ln_ff_b    = (const float*)d_in[24];
    float* out = (float*)d_out;

    k_prep<<<48, 256>>>(Wk, Wv, W_ih, W_hh, W1, W2, Wq);
    k_ln_kv<<<(B*N)/TILE_R, 256>>>(inputs, mask, bk, bv, ln_in_w, ln_in_b);
    k_init<<<B, 256>>>(noise, slots_mu, slots_sig, ln_s_w, ln_s_b, bq);
    for (int it = 0; it < ITERS; ++it) {
        k_attn<<<dim3(NB, B), 256>>>();
        k_update<<<dim3(2, B), 256>>>(b_ih, b_hh, b1, b2, ln_ff_w, ln_ff_b,
                                      ln_s_w, ln_s_b, bq, out, it == ITERS-1 ? 1 : 0);
    }
}

// round 5
// speedup vs baseline: 3.0914x; 1.2668x over previous
#include <cuda_runtime.h>
#include <cuda_fp16.h>
#include <cstdint>

// ---------------- problem constants ----------------
#define B       64
#define N       4096
#define D       64
#define H       128
#define NS      8
#define ITERS   3
#define EPSA    1e-8f
#define LN_EPS  1e-5f
#define SCALE   0.125f

#define TILE_R  64              // rows per region in kv kernel
#define NB      16              // chunks per batch in attention (256 rows each)
#define DSTR    257             // padded stride for dots/att smem

// ---------------- device scratch ----------------
__device__ __half g_kh[B*N*D];         // compacted per 64-row region, fp16
__device__ __half g_vh[B*N*D];
__device__ int    g_cnt[B*N/TILE_R];   // active rows per region
__device__ float  g_slots[B*NS*D];
__device__ float  g_q[B*NS*D];
__device__ float  g_Pp[B*NB*NS*D];
__device__ float  g_Sp[B*NB*NS];
__device__ ulonglong2 g_wk2v[16*64];   // [d4][c] packed f32x2 pairs
__device__ ulonglong2 g_wv2v[16*64];
__device__ float4 g_WgA[64*64];        // [d][dd] = (Wih_r, Wih_z, Wih_n, Whh_r)
__device__ float2 g_WgB[64*64];        // [d][dd] = (Whh_z, Whh_n)
__device__ float2 g_W1p[64*64];        // [d][h2] = (W1T[d][2h2], W1T[d][2h2+1])
__device__ float2 g_W2p[64*64];        // [h2][dd] = (W2T[2h2][dd], W2T[2h2+1][dd])
__device__ float2 g_Wqp[32*64];        // [d2][dd] = (WqT[2d2][dd], WqT[2d2+1][dd])

// ---------------- f32x2 helpers ----------------
__device__ __forceinline__ unsigned long long packf2(float x, float y) {
    unsigned long long r;
    asm("mov.b64 %0, {%1,%2};" : "=l"(r) : "f"(x), "f"(y));
    return r;
}
__device__ __forceinline__ float2 unpackf2(unsigned long long v) {
    float2 f;
    asm("mov.b64 {%0,%1}, %2;" : "=f"(f.x), "=f"(f.y) : "l"(v));
    return f;
}
__device__ __forceinline__ unsigned long long ffma2(unsigned long long a,
                                                    unsigned long long b,
                                                    unsigned long long c) {
    unsigned long long d;
    asm("fma.rn.f32x2 %0, %1, %2, %3;" : "=l"(d) : "l"(a), "l"(b), "l"(c));
    return d;
}

// dot of 16 halves (two uint4) against q[0..15]
__device__ __forceinline__ float doth16(uint4 u0, uint4 u1, const float* q) {
    const __half2* h0 = reinterpret_cast<const __half2*>(&u0);
    const __half2* h1 = reinterpret_cast<const __half2*>(&u1);
    float acc = 0.f;
    #pragma unroll
    for (int i = 0; i < 4; ++i) {
        float2 f = __half22float2(h0[i]);
        acc += f.x*q[2*i] + f.y*q[2*i+1];
    }
    #pragma unroll
    for (int i = 0; i < 4; ++i) {
        float2 f = __half22float2(h1[i]);
        acc += f.x*q[8+2*i] + f.y*q[8+2*i+1];
    }
    return acc;
}

// ---------------- prep: transpose/pack weights once ----------------
__global__ void k_prep(const float* __restrict__ Wk, const float* __restrict__ Wv,
                       const float* __restrict__ W_ih, const float* __restrict__ W_hh,
                       const float* __restrict__ W1, const float* __restrict__ W2,
                       const float* __restrict__ Wq) {
    int i = blockIdx.x * 256 + threadIdx.x;
    if (i < 1024) {                   // [16][64]
        int d4 = i >> 6, c = i & 63;
        float4 fk = *(const float4*)(Wk + c*64 + d4*4);
        float4 fv = *(const float4*)(Wv + c*64 + d4*4);
        ulonglong2 k2, v2;
        k2.x = packf2(fk.x, fk.y); k2.y = packf2(fk.z, fk.w);
        v2.x = packf2(fv.x, fv.y); v2.y = packf2(fv.z, fv.w);
        g_wk2v[i] = k2;
        g_wv2v[i] = v2;
    }
    if (i < 4096) {
        int d = i >> 6, x = i & 63;
        // GRU packed
        g_WgA[i] = make_float4(W_ih[x*64 + d], W_ih[(64+x)*64 + d],
                               W_ih[(128+x)*64 + d], W_hh[x*64 + d]);
        g_WgB[i] = make_float2(W_hh[(64+x)*64 + d], W_hh[(128+x)*64 + d]);
        // W1p: [d][h2]
        g_W1p[i] = make_float2(W1[(2*x)*64 + d], W1[(2*x+1)*64 + d]);
        // W2p: [h2][dd] where h2 = d slot, dd = x
        g_W2p[i] = make_float2(W2[x*128 + 2*d], W2[x*128 + 2*d + 1]);
    }
    if (i < 2048) {
        int d2 = i >> 6, dd = i & 63;
        g_Wqp[i] = make_float2(Wq[dd*64 + 2*d2], Wq[dd*64 + 2*d2 + 1]);
    }
}

// ---------------- K1: mask-compact + LN + k/v GEMM (compacted fp16 store) ----------------
__global__ __launch_bounds__(256, 4)
void k_ln_kv(const float* __restrict__ inputs, const int* __restrict__ mask,
             const float* __restrict__ bk, const float* __restrict__ bv,
             const float* __restrict__ lnw, const float* __restrict__ lnb) {
    __shared__ __align__(16) float xs[TILE_R*64];
    __shared__ int tpos[TILE_R];
    __shared__ int cmap[TILE_R];
    __shared__ int wc[2];

    int tid = threadIdx.x;
    int lane = tid & 31, warp = tid >> 5;
    size_t row0 = (size_t)blockIdx.x * TILE_R;

    if (tid < 64) {
        int mm = mask[row0 + tid] != 0;
        unsigned bal = __ballot_sync(~0u, mm);
        if (lane == 0) wc[warp] = __popc(bal);
        tpos[tid] = mm ? __popc(bal & ((1u << lane) - 1u)) : -1;
    }
    __syncthreads();
    int act = wc[0] + wc[1];
    if (tid < 64 && tpos[tid] >= 0)
        cmap[tpos[tid] + (tid >= 32 ? wc[0] : 0)] = tid;
    if (tid == 0) g_cnt[blockIdx.x] = act;
    __syncthreads();

    {
        float lw0 = lnw[lane], lw1 = lnw[lane+32];
        float lb0 = lnb[lane], lb1 = lnb[lane+32];
        for (int ci = warp; ci < act; ci += 8) {
            int r = cmap[ci];
            const float* src = inputs + (row0 + r)*64;
            float v0 = src[lane], v1 = src[lane+32];
            float s = v0 + v1;
            #pragma unroll
            for (int o = 16; o; o >>= 1) s += __shfl_xor_sync(~0u, s, o);
            float mu = s * (1.f/64.f);
            float d0 = v0 - mu, d1 = v1 - mu;
            float q = d0*d0 + d1*d1;
            #pragma unroll
            for (int o = 16; o; o >>= 1) q += __shfl_xor_sync(~0u, q, o);
            float rs = rsqrtf(q * (1.f/64.f) + LN_EPS);
            xs[ci*64 + lane]      = d0*rs*lw0 + lb0;
            xs[ci*64 + 32 + lane] = d1*rs*lw1 + lb1;
        }
    }
    __syncthreads();

    int c  = tid & 63;
    int rb = tid >> 6;
    float bkc = bk[c], bvc = bv[c];
    const ulonglong2* xs2 = reinterpret_cast<const ulonglong2*>(xs);
    int G = (act + 31) >> 5;
    for (int g = 0; g < G; ++g) {
        unsigned long long ak[8], av[8];
        #pragma unroll
        for (int t = 0; t < 8; ++t) { ak[t] = 0ull; av[t] = 0ull; }
        #pragma unroll
        for (int d4 = 0; d4 < 16; ++d4) {
            ulonglong2 wk = __ldg(g_wk2v + d4*64 + c);
            ulonglong2 wv = __ldg(g_wv2v + d4*64 + c);
            #pragma unroll
            for (int t = 0; t < 8; ++t) {
                int ci = g*32 + rb + 4*t;
                ulonglong2 x = xs2[ci*16 + d4];
                ak[t] = ffma2(x.x, wk.x, ak[t]);
                ak[t] = ffma2(x.y, wk.y, ak[t]);
                av[t] = ffma2(x.x, wv.x, av[t]);
                av[t] = ffma2(x.y, wv.y, av[t]);
            }
        }
        #pragma unroll
        for (int t = 0; t < 8; ++t) {
            int ci = g*32 + rb + 4*t;
            if (ci < act) {
                float2 k2 = unpackf2(ak[t]);
                float2 v2 = unpackf2(av[t]);
                g_kh[(row0 + ci)*64 + c] = __float2half_rn(k2.x + k2.y + bkc);
                g_vh[(row0 + ci)*64 + c] = __float2half_rn(v2.x + v2.y + bvc);
            }
        }
    }
    // pad rows [act, pad8) are never written by any run -> remain zero (device bss)
}

// ---------------- LN over slot rows ----------------
__device__ __forceinline__ void lnrows(const float* in, float* out,
                                       const float* __restrict__ w,
                                       const float* __restrict__ bia, int tid, int nrows) {
    int wp = tid >> 5, lane = tid & 31;
    if (wp >= nrows) return;
    const float* p = in + wp*64;
    float v0 = p[lane], v1 = p[lane+32];
    float s = v0 + v1;
    #pragma unroll
    for (int o = 16; o; o >>= 1) s += __shfl_xor_sync(~0u, s, o);
    float mu = s * (1.f/64.f);
    float d0 = v0 - mu, d1 = v1 - mu;
    float q = d0*d0 + d1*d1;
    #pragma unroll
    for (int o = 16; o; o >>= 1) q += __shfl_xor_sync(~0u, q, o);
    float rs = rsqrtf(q * (1.f/64.f) + LN_EPS);
    out[wp*64 + lane]      = d0*rs*w[lane] + bia[lane];
    out[wp*64 + lane + 32] = d1*rs*w[lane+32] + bia[lane+32];
}

// ---------------- init: slots = mu + sigma*noise; q0 ----------------
__global__ __launch_bounds__(256)
void k_init(const float* __restrict__ noise, const float* __restrict__ mu,
            const float* __restrict__ sg,
            const float* __restrict__ ln_s_w, const float* __restrict__ ln_s_b,
            const float* __restrict__ bq) {
    __shared__ float sl[512], sn[512];
    int b = blockIdx.x, tid = threadIdx.x;
    #pragma unroll
    for (int u = 0; u < 2; ++u) {
        int t = tid + 256*u, dd = t & 63;
        float s = mu[dd] + sg[dd]*noise[b*512 + t];
        sl[t] = s;
        g_slots[b*512 + t] = s;
    }
    __syncthreads();
    lnrows(sl, sn, ln_s_w, ln_s_b, tid, 8);
    __syncthreads();
    #pragma unroll
    for (int u = 0; u < 2; ++u) {
        int t = tid + 256*u, j = t >> 6, dd = t & 63;
        float acc = bq[dd];
        const float2* sj2 = (const float2*)(sn + j*64);
        #pragma unroll 8
        for (int d2 = 0; d2 < 32; ++d2) {
            float2 w = g_Wqp[d2*64 + dd];
            float2 s2 = sj2[d2];
            acc += s2.x*w.x + s2.y*w.y;
        }
        g_q[b*512 + t] = acc * SCALE;
    }
}

// ---------------- attention: fp16 k/v, padded uniform loops, in-thread softmax ----------------
__global__ __launch_bounds__(256)
void k_attn() {
    __shared__ float dots[8*DSTR];
    __shared__ float att[8*DSTR];
    __shared__ float redP[8*512];
    __shared__ float redS[64];
    __shared__ int   cnts[4];

    int b = blockIdx.y, chunk = blockIdx.x;
    int tid = threadIdx.x;
    int warp = tid >> 5, lane = tid & 31;
    int jj = lane & 7;
    int gg = lane >> 3;

    if (tid < 4) cnts[tid] = g_cnt[b*(N/TILE_R) + chunk*4 + tid];

    float q[16];
    {
        const float4* qp = (const float4*)(g_q + b*512 + jj*64) + (gg << 2);
        #pragma unroll
        for (int i = 0; i < 4; ++i) {
            float4 t4 = qp[i];
            q[4*i] = t4.x; q[4*i+1] = t4.y; q[4*i+2] = t4.z; q[4*i+3] = t4.w;
        }
    }
    __syncthreads();

    // Phase A: dots
    #pragma unroll
    for (int s = 0; s < 4; ++s) {
        int nit = (cnts[s] + 7) >> 3;
        const __half* kb = g_kh + ((size_t)(b*(N/TILE_R) + chunk*4 + s) * TILE_R) * 64;
        #pragma unroll 2
        for (int it = 0; it < nit; ++it) {
            int r = it*8 + warp;
            const uint4* kp = (const uint4*)(kb + r*64) + gg*2;
            uint4 u0 = kp[0], u1 = kp[1];
            float d = doth16(u0, u1, q);
            d += __shfl_xor_sync(~0u, d, 8);
            d += __shfl_xor_sync(~0u, d, 16);
            if (gg == 0) dots[jj*DSTR + s*64 + r] = d;
        }
    }
    __syncthreads();

    // Phase B: in-thread softmax (1 thread per row); zero att on pad rows
    {
        int s = tid >> 6, r = tid & 63;
        int act = cnts[s];
        int pad8 = (act + 7) & ~7;
        if (r < act) {
            float d[8];
            #pragma unroll
            for (int j = 0; j < 8; ++j) d[j] = dots[j*DSTR + tid];
            float m = d[0];
            #pragma unroll
            for (int j = 1; j < 8; ++j) m = fmaxf(m, d[j]);
            float e[8], sum = 0.f;
            #pragma unroll
            for (int j = 0; j < 8; ++j) { e[j] = __expf(d[j] - m); sum += e[j]; }
            float inv = __fdividef(1.f, sum);
            #pragma unroll
            for (int j = 0; j < 8; ++j) att[j*DSTR + tid] = e[j]*inv + EPSA;
        } else if (r < pad8) {
            #pragma unroll
            for (int j = 0; j < 8; ++j) att[j*DSTR + tid] = 0.f;
        }
    }
    __syncthreads();

    // Phase C: P accumulation
    float P[16];
    #pragma unroll
    for (int i = 0; i < 16; ++i) P[i] = 0.f;
    float S = 0.f;
    #pragma unroll
    for (int s = 0; s < 4; ++s) {
        int nit = (cnts[s] + 7) >> 3;
        const __half* vb = g_vh + ((size_t)(b*(N/TILE_R) + chunk*4 + s) * TILE_R) * 64;
        #pragma unroll 2
        for (int it = 0; it < nit; ++it) {
            int r = it*8 + warp;
            float a = att[jj*DSTR + s*64 + r];
            S += a;
            const uint4* vp = (const uint4*)(vb + r*64) + gg*2;
            uint4 u0 = vp[0], u1 = vp[1];
            const __half2* h0 = reinterpret_cast<const __half2*>(&u0);
            const __half2* h1 = reinterpret_cast<const __half2*>(&u1);
            #pragma unroll
            for (int i = 0; i < 4; ++i) {
                float2 f = __half22float2(h0[i]);
                P[2*i]   += a*f.x;
                P[2*i+1] += a*f.y;
            }
            #pragma unroll
            for (int i = 0; i < 4; ++i) {
                float2 f = __half22float2(h1[i]);
                P[8+2*i]   += a*f.x;
                P[8+2*i+1] += a*f.y;
            }
        }
    }

    float* rp = redP + warp*512 + jj*64 + (gg << 4);
    #pragma unroll
    for (int i = 0; i < 4; ++i)
        *(float4*)(rp + 4*i) = make_float4(P[4*i], P[4*i+1], P[4*i+2], P[4*i+3]);
    if (gg == 0) redS[warp*8 + jj] = S;
    __syncthreads();

    #pragma unroll
    for (int u = 0; u < 2; ++u) {
        int t = tid + 256*u;
        float s = 0.f;
        #pragma unroll
        for (int w = 0; w < 8; ++w) s += redP[w*512 + t];
        g_Pp[((size_t)b*NB + chunk)*512 + t] = s;
    }
    if (tid < 8) {
        float s = 0.f;
        #pragma unroll
        for (int w = 0; w < 8; ++w) s += redS[w*8 + tid];
        g_Sp[(b*NB + chunk)*8 + tid] = s;
    }
}

// ---------------- slot update: GRU + residual MLP (+ next q); 4 slots/block ----------------
__global__ __launch_bounds__(256)
void k_update(const float* __restrict__ b_ih, const float* __restrict__ b_hh,
              const float* __restrict__ b1, const float* __restrict__ b2,
              const float* __restrict__ ln_ff_w, const float* __restrict__ ln_ff_b,
              const float* __restrict__ ln_s_w, const float* __restrict__ ln_s_b,
              const float* __restrict__ bq,
              float* __restrict__ d_out, int last) {
    __shared__ float upd[256], prev[256], snew[256], ffs[256], hid[512], sfin[256], Ssm[4];
    int b = blockIdx.y, half = blockIdx.x, tid = threadIdx.x;
    int j0 = half * 4;
    int j = tid >> 6, dd = tid & 63;
    int J = j0 + j;

    if (tid < 4) {
        float s = 0.f;
        const float* sp = g_Sp + b*NB*8 + j0 + tid;
        #pragma unroll
        for (int p = 0; p < NB; ++p) s += sp[p*8];
        Ssm[tid] = s;
    }
    float pr;
    {
        float s = 0.f;
        const float* pp = g_Pp + (size_t)b*NB*512 + J*64 + dd;
        #pragma unroll
        for (int p = 0; p < NB; ++p) s += pp[p*512];
        pr = s;
        prev[tid] = g_slots[b*512 + J*64 + dd];
    }
    __syncthreads();
    upd[tid] = pr / Ssm[j];
    __syncthreads();

    // GRU with packed weights: 1 LDG.128 + 1 LDG.64 per d
    {
        const float* uj = upd + j*64;
        const float* hj = prev + j*64;
        float xr = b_ih[dd], xz = b_ih[64+dd], xn = b_ih[128+dd];
        float hr = b_hh[dd], hz = b_hh[64+dd], hn = b_hh[128+dd];
        #pragma unroll 8
        for (int d = 0; d < 64; ++d) {
            float uu = uj[d], hh = hj[d];
            float4 wa = __ldg(g_WgA + d*64 + dd);
            float2 wb = __ldg(g_WgB + d*64 + dd);
            xr += uu*wa.x; xz += uu*wa.y; xn += uu*wa.z;
            hr += hh*wa.w; hz += hh*wb.x; hn += hh*wb.y;
        }
        float rg = 1.f/(1.f + __expf(-(xr + hr)));
        float zg = 1.f/(1.f + __expf(-(xz + hz)));
        float t2 = __expf(2.f*(xn + rg*hn));
        float nn = 1.f - 2.f/(t2 + 1.f);
        snew[tid] = (1.f - zg)*nn + zg*prev[tid];
    }
    __syncthreads();
    lnrows(snew, ffs, ln_ff_w, ln_ff_b, tid, 4);
    __syncthreads();
    // MLP layer 1: thread owns (j, h-pair)
    {
        int h2 = dd;               // 0..63 -> h = 2*h2, 2*h2+1
        float a0 = b1[2*h2], a1 = b1[2*h2+1];
        const float* fj = ffs + j*64;
        #pragma unroll 8
        for (int d = 0; d < 64; ++d) {
            float2 w = __ldg(g_W1p + d*64 + h2);
            float f = fj[d];
            a0 += f*w.x; a1 += f*w.y;
        }
        hid[j*128 + 2*h2]   = fmaxf(a0, 0.f);
        hid[j*128 + 2*h2+1] = fmaxf(a1, 0.f);
    }
    __syncthreads();
    {
        float acc = b2[dd];
        const float2* hj2 = (const float2*)(hid + j*128);
        #pragma unroll 8
        for (int h2 = 0; h2 < 64; ++h2) {
            float2 w = __ldg(g_W2p + h2*64 + dd);
            float2 hv = hj2[h2];
            acc += hv.x*w.x + hv.y*w.y;
        }
        float o = snew[tid] + acc;
        sfin[tid] = o;
        g_slots[b*512 + J*64 + dd] = o;
        if (last) d_out[b*512 + J*64 + dd] = o;
    }
    if (!last) {
        __syncthreads();
        lnrows(sfin, ffs, ln_s_w, ln_s_b, tid, 4);
        __syncthreads();
        {
            float acc = bq[dd];
            const float2* sj2 = (const float2*)(ffs + j*64);
            #pragma unroll 8
            for (int d2 = 0; d2 < 32; ++d2) {
                float2 w = __ldg(g_Wqp + d2*64 + dd);
                float2 s2 = sj2[d2];
                acc += s2.x*w.x + s2.y*w.y;
            }
            g_q[b*512 + J*64 + dd] = acc * SCALE;
        }
    }
}

// ---------------- launch ----------------
extern "C" void kernel_launch(void* const* d_in, const int* in_sizes, int n_in,
                              void* d_out, int out_size) {
    const float* inputs     = (const float*)d_in[0];
    const int*   mask       = (const int*)  d_in[1];
    const float* noise      = (const float*)d_in[2];
    const float* slots_mu   = (const float*)d_in[3];
    const float* slots_sig  = (const float*)d_in[4];
    const float* Wq         = (const float*)d_in[5];
    const float* bq         = (const float*)d_in[6];
    const float* Wk         = (const float*)d_in[7];
    const float* bk         = (const float*)d_in[8];
    const float* Wv         = (const float*)d_in[9];
    const float* bv         = (const float*)d_in[10];
    const float* W_ih       = (const float*)d_in[11];
    const float* b_ih       = (const float*)d_in[12];
    const float* W_hh       = (const float*)d_in[13];
    const float* b_hh       = (const float*)d_in[14];
    const float* W1         = (const float*)d_in[15];
    const float* b1         = (const float*)d_in[16];
    const float* W2         = (const float*)d_in[17];
    const float* b2         = (const float*)d_in[18];
    const float* ln_in_w    = (const float*)d_in[19];
    const float* ln_in_b    = (const float*)d_in[20];
    const float* ln_s_w     = (const float*)d_in[21];
    const float* ln_s_b     = (const float*)d_in[22];
    const float* ln_ff_w    = (const float*)d_in[23];
    const float* ln_ff_b    = (const float*)d_in[24];
    float* out = (float*)d_out;

    k_prep<<<48, 256>>>(Wk, Wv, W_ih, W_hh, W1, W2, Wq);
    k_ln_kv<<<(B*N)/TILE_R, 256>>>(inputs, mask, bk, bv, ln_in_w, ln_in_b);
    k_init<<<B, 256>>>(noise, slots_mu, slots_sig, ln_s_w, ln_s_b, bq);
    for (int it = 0; it < ITERS; ++it) {
        k_attn<<<dim3(NB, B), 256>>>();
        k_update<<<dim3(2, B), 256>>>(b_ih, b_hh, b1, b2, ln_ff_w, ln_ff_b,
                                      ln_s_w, ln_s_b, bq, out, it == ITERS-1 ? 1 : 0);
    }
}